// round 1
// baseline (speedup 1.0000x reference)
#include <cuda_runtime.h>
#include <math.h>

#define DET 512
#define NTH 180
#define B   4
#define OUT 362
#define RAD 181          // OUT/2
#define PI_F 3.14159265358979323846f

// filtered projections, layout [b][a][det] (det contiguous)
__device__ float g_filt[B * NTH * DET];

// ---------------------------------------------------------------------------
// Kernel 1: ramp filter as direct symmetric convolution.
// filtered[b,k,a] = 0.5*x[b,k,a] + sum_{|k-m| odd} (-2/(pi*(k-m))^2) * x[b,m,a]
// grid (NTH, B), block DET threads. Writes g_filt[b][a][k].
// ---------------------------------------------------------------------------
__global__ void __launch_bounds__(DET) filter_kernel(const float* __restrict__ x)
{
    __shared__ float xs[DET];
    __shared__ float gt[DET];

    const int a = blockIdx.x;
    const int b = blockIdx.y;
    const int k = threadIdx.x;

    // x layout: (B,1,DET,NTH) -> x[b, m, a] = x[(b*DET + m)*NTH + a]
    xs[k] = x[(b * DET + k) * NTH + a];

    // g table: only odd distances are nonzero (d=0 handled separately)
    float fd = (float)k;
    gt[k] = (k & 1) ? (-2.0f / (PI_F * PI_F * fd * fd)) : 0.0f;
    __syncthreads();

    float s = 0.5f * xs[k];
    const int par = (k & 1) ^ 1;   // m-parity opposite to k
    #pragma unroll 8
    for (int i = 0; i < DET / 2; i++) {
        int m = 2 * i + par;
        int d = k - m; d = d < 0 ? -d : d;
        s = fmaf(gt[d], xs[m], s);
    }
    g_filt[(b * NTH + a) * DET + k] = s;
}

// ---------------------------------------------------------------------------
// Kernel 2: backprojection. 32x32 pixel tile per block, 32x8 threads,
// 4 pixels per thread (rows i stride 8). Per angle: stage 512-float
// detector row in shared, then lerp-gather.
// pos = (j-RAD)*cos(th) - (i-RAD)*sin(th) + DET/2
// ---------------------------------------------------------------------------
__global__ void __launch_bounds__(256) backproj_kernel(float* __restrict__ out)
{
    __shared__ float row[DET];
    __shared__ float cs[NTH];
    __shared__ float sn[NTH];

    const int b  = blockIdx.z;
    const int j0 = blockIdx.x * 32;
    const int i0 = blockIdx.y * 32;
    const int tx = threadIdx.x;          // 0..31 -> column j
    const int ty = threadIdx.y;          // 0..7  -> row group
    const int tid = ty * 32 + tx;

    if (tid < NTH) {
        float ang = (float)tid * (PI_F / 180.0f);
        cs[tid] = cosf(ang);
        sn[tid] = sinf(ang);
    }
    __syncthreads();

    const int j = j0 + tx;
    const float yp = (float)(j - RAD);
    const float xp0 = (float)(i0 + ty - RAD);

    const float* fb = g_filt + b * NTH * DET;

    float acc0 = 0.f, acc1 = 0.f, acc2 = 0.f, acc3 = 0.f;

    for (int a = 0; a < NTH; a++) {
        row[tid]       = fb[a * DET + tid];
        row[tid + 256] = fb[a * DET + tid + 256];
        __syncthreads();

        const float c = cs[a];
        const float s = sn[a];
        const float base = fmaf(yp, c, (float)(DET / 2));

        #pragma unroll
        for (int r = 0; r < 4; r++) {
            float pos = fmaf(-(xp0 + 8.0f * (float)r), s, base);
            if (pos >= 0.0f && pos <= (float)(DET - 1)) {
                float fl = floorf(pos);
                int   idx = (int)fl;
                float w = pos - fl;
                float v0 = row[idx];
                int   idx1 = idx + 1 < DET ? idx + 1 : DET - 1;
                float v1 = row[idx1];
                float v = fmaf(w, v1 - v0, v0);
                if      (r == 0) acc0 += v;
                else if (r == 1) acc1 += v;
                else if (r == 2) acc2 += v;
                else             acc3 += v;
            }
        }
        __syncthreads();
    }

    const float scale = PI_F / (2.0f * (float)NTH);
    if (j < OUT) {
        float accs[4] = {acc0, acc1, acc2, acc3};
        #pragma unroll
        for (int r = 0; r < 4; r++) {
            int i = i0 + ty + 8 * r;
            if (i < OUT)
                out[(b * OUT + i) * OUT + j] = accs[r] * scale;
        }
    }
}

extern "C" void kernel_launch(void* const* d_in, const int* in_sizes, int n_in,
                              void* d_out, int out_size)
{
    const float* x = (const float*)d_in[0];
    float* out = (float*)d_out;

    filter_kernel<<<dim3(NTH, B), DET>>>(x);

    dim3 grid((OUT + 31) / 32, (OUT + 31) / 32, B);   // 12 x 12 x 4
    backproj_kernel<<<grid, dim3(32, 8)>>>(out);
}